// round 3
// baseline (speedup 1.0000x reference)
#include <cuda_runtime.h>
#include <cstdint>

#define BATCH   262144
#define NIN     9
#define NHID    100
#define NOUT    2
#define TSTEPS  25
#define BETA    0.95f

// One-instruction FSET: returns 1.0f if a > b else 0.0f
__device__ __forceinline__ float fset_gt(float a, float b) {
    float d; asm("set.gt.f32.f32 %0, %1, %2;" : "=f"(d) : "f"(a), "f"(b)); return d;
}

__global__ __launch_bounds__(256) void snn_kernel(
    const float* __restrict__ x,  const float* __restrict__ W1,
    const float* __restrict__ b1, const float* __restrict__ W2,
    const float* __restrict__ b2, float* __restrict__ out)
{
    __shared__ float sW1[NHID * NIN];
    __shared__ float sb1[NHID];
    __shared__ float sW2[NOUT * NHID];

    for (int i = threadIdx.x; i < NHID * NIN; i += blockDim.x) sW1[i] = W1[i];
    for (int i = threadIdx.x; i < NHID;       i += blockDim.x) sb1[i] = b1[i];
    for (int i = threadIdx.x; i < NOUT*NHID;  i += blockDim.x) sW2[i] = W2[i];
    __syncthreads();

    const int b = blockIdx.x * blockDim.x + threadIdx.x;  // one thread per element

    float xr[NIN];
    #pragma unroll
    for (int i = 0; i < NIN; i++) xr[i] = __ldg(&x[b * NIN + i]);

    // Per-timestep partial sums of cur2 (before bias), built in ascending-h
    // serial order so they bit-match a serial-K fma chain (cublas-style).
    float acc0[TSTEPS], acc1[TSTEPS];
    #pragma unroll
    for (int t = 0; t < TSTEPS; t++) { acc0[t] = 0.0f; acc1[t] = 0.0f; }

    // Outer loop over hidden units (rolled: keeps SASS body ~3KB, in I$).
    #pragma unroll 1
    for (int h = 0; h < NHID; h++) {
        // cur1[h]: serial ascending-k fma chain from 0, bias added last.
        float c = 0.0f;
        #pragma unroll
        for (int k = 0; k < NIN; k++) c = fmaf(xr[k], sW1[h * NIN + k], c);
        c = __fadd_rn(c, sb1[h]);

        const float w0 = sW2[h];
        const float w1 = sW2[NHID + h];

        // 25-step LIF recurrence for this hidden unit, one register of state.
        // Exactly: reset = spike(mem_old - 1); mem = ((b*mem)+cur) - reset;
        // spk = spike(mem - 1). No FMA contraction (matches XLA elementwise).
        float m = 0.0f;
        #pragma unroll
        for (int t = 0; t < TSTEPS; t++) {
            const float r = fset_gt(m, 1.0f);                       // reset = prev spike
            m = __fsub_rn(__fadd_rn(__fmul_rn(BETA, m), c), r);     // separate mul/add/sub
            const float s = fset_gt(m, 1.0f);                       // spk1
            acc0[t] = fmaf(s, w0, acc0[t]);                         // serial-h chain, out 0
            acc1[t] = fmaf(s, w1, acc1[t]);                         // serial-h chain, out 1
        }
    }

    // Output layer recurrence + stores.
    const float b20 = __ldg(&b2[0]);
    const float b21 = __ldg(&b2[1]);
    float m0 = 0.0f, m1 = 0.0f;

    float2* pspk = (float2*)out + (size_t)b;                          // spk2_rec [25,B,2]
    float2* pmem = (float2*)out + (size_t)TSTEPS * BATCH + (size_t)b; // mem2_rec [25,B,2]

    #pragma unroll
    for (int t = 0; t < TSTEPS; t++) {
        const float c0 = __fadd_rn(acc0[t], b20);
        const float c1 = __fadd_rn(acc1[t], b21);

        const float r0 = fset_gt(m0, 1.0f);
        m0 = __fsub_rn(__fadd_rn(__fmul_rn(BETA, m0), c0), r0);
        const float s0 = fset_gt(m0, 1.0f);

        const float r1 = fset_gt(m1, 1.0f);
        m1 = __fsub_rn(__fadd_rn(__fmul_rn(BETA, m1), c1), r1);
        const float s1 = fset_gt(m1, 1.0f);

        pspk[(size_t)t * BATCH] = make_float2(s0, s1);
        pmem[(size_t)t * BATCH] = make_float2(m0, m1);
    }
}

extern "C" void kernel_launch(void* const* d_in, const int* in_sizes, int n_in,
                              void* d_out, int out_size) {
    const float* x  = (const float*)d_in[0];
    const float* W1 = (const float*)d_in[1];
    const float* b1 = (const float*)d_in[2];
    const float* W2 = (const float*)d_in[3];
    const float* b2 = (const float*)d_in[4];
    float* out = (float*)d_out;

    const int threads = 256;
    snn_kernel<<<BATCH / threads, threads>>>(x, W1, b1, W2, b2, out);
}

// round 4
// speedup vs baseline: 1.1636x; 1.1636x over previous
#include <cuda_runtime.h>
#include <cstdint>

#define BATCH   262144
#define NIN     9
#define NHID    100
#define NPAIR   50
#define NOUT    2
#define TSTEPS  25
#define BETA    0.95f

typedef unsigned long long u64;

__device__ __forceinline__ u64 pack2(float lo, float hi) {
    u64 r; asm("mov.b64 %0, {%1, %2};" : "=l"(r) : "f"(lo), "f"(hi)); return r;
}
__device__ __forceinline__ void unpack2(u64 v, float& lo, float& hi) {
    asm("mov.b64 {%0, %1}, %2;" : "=f"(lo), "=f"(hi) : "l"(v));
}
__device__ __forceinline__ u64 fma2(u64 a, u64 b, u64 c) {
    u64 d; asm("fma.rn.f32x2 %0, %1, %2, %3;" : "=l"(d) : "l"(a), "l"(b), "l"(c)); return d;
}
__device__ __forceinline__ u64 mul2(u64 a, u64 b) {
    u64 d; asm("mul.rn.f32x2 %0, %1, %2;" : "=l"(d) : "l"(a), "l"(b)); return d;
}
__device__ __forceinline__ u64 add2(u64 a, u64 b) {
    u64 d; asm("add.rn.f32x2 %0, %1, %2;" : "=l"(d) : "l"(a), "l"(b)); return d;
}
// One-instruction FSET: 1.0f if a > b else 0.0f
__device__ __forceinline__ float fset_gt(float a, float b) {
    float d; asm("set.gt.f32.f32 %0, %1, %2;" : "=f"(d) : "f"(a), "f"(b)); return d;
}

__global__ __launch_bounds__(256) void snn_kernel(
    const float* __restrict__ x,  const float* __restrict__ W1,
    const float* __restrict__ b1, const float* __restrict__ W2,
    const float* __restrict__ b2, float* __restrict__ out)
{
    // W1 re-laid-out as interleaved unit-pairs: sW1p[p*NIN+k] = (W1[2p][k], W1[2p+1][k])
    __shared__ float2 sW1p[NPAIR * NIN];
    __shared__ float2 sb1p[NPAIR];                 // (b1[2p], b1[2p+1])
    __shared__ float2 sw0p[NPAIR], sw1p[NPAIR];    // W2 rows as adjacent pairs

    for (int i = threadIdx.x; i < NHID * NIN; i += blockDim.x) {
        int h = i / NIN, k = i % NIN;
        ((float*)&sW1p[(h >> 1) * NIN + k])[h & 1] = W1[i];
    }
    for (int i = threadIdx.x; i < NPAIR; i += blockDim.x) {
        sb1p[i] = make_float2(b1[2*i],        b1[2*i + 1]);
        sw0p[i] = make_float2(W2[2*i],        W2[2*i + 1]);
        sw1p[i] = make_float2(W2[NHID + 2*i], W2[NHID + 2*i + 1]);
    }
    __syncthreads();

    const int b = blockIdx.x * blockDim.x + threadIdx.x;  // one thread per element

    // Broadcast-packed input row: xp[k] = (x_k, x_k)
    u64 xp[NIN];
    #pragma unroll
    for (int k = 0; k < NIN; k++) {
        const float xv = __ldg(&x[b * NIN + k]);
        xp[k] = pack2(xv, xv);
    }

    // Per-timestep cur2 partial sums, serial ascending-h chain (bit-matches cublas).
    float acc0[TSTEPS], acc1[TSTEPS];
    #pragma unroll
    for (int t = 0; t < TSTEPS; t++) { acc0[t] = 0.0f; acc1[t] = 0.0f; }

    const u64 BETA2 = pack2(BETA, BETA);
    const u64 NEG2  = pack2(-1.0f, -1.0f);

    #pragma unroll 1
    for (int p = 0; p < NPAIR; p++) {
        // Packed cur1 pair: serial ascending-k fma chain from 0, bias added last.
        // Per-lane rounding identical to scalar fmaf chain.
        u64 cp = 0ull;
        #pragma unroll
        for (int k = 0; k < NIN; k++) {
            const float2 w = sW1p[p * NIN + k];
            cp = fma2(xp[k], pack2(w.x, w.y), cp);
        }
        const float2 bb = sb1p[p];
        cp = add2(cp, pack2(bb.x, bb.y));

        const float2 w0 = sw0p[p];
        const float2 w1 = sw1p[p];

        // 25-step LIF for 2 hidden units in packed lanes.
        // reset(t) == spike(t-1): reuse rp. fma(r,-1,bc) single-rounds bc-r (exact product).
        u64 m = 0ull, rp = 0ull;
        #pragma unroll
        for (int t = 0; t < TSTEPS; t++) {
            const u64 bm = mul2(BETA2, m);     // beta*mem   (separate rounding)
            const u64 bc = add2(bm, cp);       // + cur      (separate rounding)
            m = fma2(rp, NEG2, bc);            // - reset    (== __fsub_rn(bc, r))
            float mlo, mhi; unpack2(m, mlo, mhi);
            const float slo = fset_gt(mlo, 1.0f);
            const float shi = fset_gt(mhi, 1.0f);
            rp = pack2(slo, shi);
            // serial-h accumulation: unit 2p then 2p+1
            acc0[t] = fmaf(slo, w0.x, acc0[t]);
            acc0[t] = fmaf(shi, w0.y, acc0[t]);
            acc1[t] = fmaf(slo, w1.x, acc1[t]);
            acc1[t] = fmaf(shi, w1.y, acc1[t]);
        }
    }

    // Output layer recurrence + coalesced stores.
    const float b20 = __ldg(&b2[0]);
    const float b21 = __ldg(&b2[1]);
    float m0 = 0.0f, m1 = 0.0f;
    float s0 = 0.0f, s1 = 0.0f;   // spike == next step's reset

    float2* pspk = (float2*)out + (size_t)b;                          // spk2_rec [25,B,2]
    float2* pmem = (float2*)out + (size_t)TSTEPS * BATCH + (size_t)b; // mem2_rec [25,B,2]

    #pragma unroll
    for (int t = 0; t < TSTEPS; t++) {
        const float c0 = __fadd_rn(acc0[t], b20);
        const float c1 = __fadd_rn(acc1[t], b21);

        m0 = __fsub_rn(__fadd_rn(__fmul_rn(BETA, m0), c0), s0);
        s0 = fset_gt(m0, 1.0f);

        m1 = __fsub_rn(__fadd_rn(__fmul_rn(BETA, m1), c1), s1);
        s1 = fset_gt(m1, 1.0f);

        pspk[(size_t)t * BATCH] = make_float2(s0, s1);
        pmem[(size_t)t * BATCH] = make_float2(m0, m1);
    }
}

extern "C" void kernel_launch(void* const* d_in, const int* in_sizes, int n_in,
                              void* d_out, int out_size) {
    const float* x  = (const float*)d_in[0];
    const float* W1 = (const float*)d_in[1];
    const float* b1 = (const float*)d_in[2];
    const float* W2 = (const float*)d_in[3];
    const float* b2 = (const float*)d_in[4];
    float* out = (float*)d_out;

    const int threads = 256;
    snn_kernel<<<BATCH / threads, threads>>>(x, W1, b1, W2, b2, out);
}

// round 5
// speedup vs baseline: 1.2423x; 1.0676x over previous
#include <cuda_runtime.h>
#include <cstdint>

#define BATCH   262144
#define NIN     9
#define NHID    100
#define NPAIR   50
#define NOUT    2
#define TSTEPS  25
#define BETA    0.95f

typedef unsigned long long u64;

__device__ __forceinline__ u64 pack2(float lo, float hi) {
    u64 r; asm("mov.b64 %0, {%1, %2};" : "=l"(r) : "f"(lo), "f"(hi)); return r;
}
__device__ __forceinline__ void unpack2(u64 v, float& lo, float& hi) {
    asm("mov.b64 {%0, %1}, %2;" : "=f"(lo), "=f"(hi) : "l"(v));
}
__device__ __forceinline__ u64 fma2(u64 a, u64 b, u64 c) {
    u64 d; asm("fma.rn.f32x2 %0, %1, %2, %3;" : "=l"(d) : "l"(a), "l"(b), "l"(c)); return d;
}
__device__ __forceinline__ u64 mul2(u64 a, u64 b) {
    u64 d; asm("mul.rn.f32x2 %0, %1, %2;" : "=l"(d) : "l"(a), "l"(b)); return d;
}
__device__ __forceinline__ u64 add2(u64 a, u64 b) {
    u64 d; asm("add.rn.f32x2 %0, %1, %2;" : "=l"(d) : "l"(a), "l"(b)); return d;
}
// FSET: 1.0f if a > 1.0f else 0.0f
__device__ __forceinline__ float fset_gt1(float a) {
    float d; asm("set.gt.f32.f32 %0, %1, 0f3F800000;" : "=f"(d) : "f"(a)); return d;
}

__global__ __launch_bounds__(128) void snn_kernel(
    const float* __restrict__ x,  const float* __restrict__ W1,
    const float* __restrict__ b1, const float* __restrict__ W2,
    const float* __restrict__ b2, float* __restrict__ out)
{
    // W1 interleaved unit-pairs as u64: sW1p[p*NIN+k] = (W1[2p][k], W1[2p+1][k])
    __shared__ u64 sW1p[NPAIR * NIN];
    __shared__ u64 sb1p[NPAIR];      // (b1[2p], b1[2p+1])
    // W2 interleaved OUTPUT-pairs: sw2i[h] = (W2[0][h], W2[1][h])
    __shared__ u64 sw2i[NHID];

    for (int i = threadIdx.x; i < NHID * NIN; i += blockDim.x) {
        int h = i / NIN, k = i % NIN;
        ((float*)&sW1p[(h >> 1) * NIN + k])[h & 1] = W1[i];
    }
    for (int i = threadIdx.x; i < NPAIR; i += blockDim.x) {
        ((float*)&sb1p[i])[0] = b1[2*i];
        ((float*)&sb1p[i])[1] = b1[2*i + 1];
    }
    for (int i = threadIdx.x; i < NHID; i += blockDim.x) {
        ((float*)&sw2i[i])[0] = W2[i];          // output 0 weight for unit i
        ((float*)&sw2i[i])[1] = W2[NHID + i];   // output 1 weight for unit i
    }
    __syncthreads();

    const int b = blockIdx.x * blockDim.x + threadIdx.x;  // one thread per element

    // Broadcast-packed input row: xp[k] = (x_k, x_k)
    u64 xp[NIN];
    #pragma unroll
    for (int k = 0; k < NIN; k++) {
        const float xv = __ldg(&x[b * NIN + k]);
        xp[k] = pack2(xv, xv);
    }

    // Packed per-timestep cur2 partials: lane0 = output-0 chain, lane1 = output-1 chain.
    // Each lane is a serial ascending-h scalar fma chain (bit-matches cublas serial-K).
    u64 accP[TSTEPS];
    #pragma unroll
    for (int t = 0; t < TSTEPS; t++) accP[t] = 0ull;

    const u64 BETA2 = pack2(BETA, BETA);
    const u64 NEG2  = pack2(-1.0f, -1.0f);

    #pragma unroll 1
    for (int p = 0; p < NPAIR; p++) {
        // Packed cur1 pair: serial ascending-k fma chain from 0, bias added last.
        u64 cp = 0ull;
        #pragma unroll
        for (int k = 0; k < NIN; k++) cp = fma2(xp[k], sW1p[p * NIN + k], cp);
        cp = add2(cp, sb1p[p]);

        const u64 wA = sw2i[2 * p];       // (W2[0][2p],   W2[1][2p])
        const u64 wB = sw2i[2 * p + 1];   // (W2[0][2p+1], W2[1][2p+1])

        // 25-step LIF for 2 hidden units (membrane packed as (h_even, h_odd)).
        // reset(t) == spike(t-1). fma2(rp,-1,bc) == per-lane __fsub_rn(bc, r).
        u64 m = 0ull, rp = 0ull;
        #pragma unroll
        for (int t = 0; t < TSTEPS; t++) {
            const u64 bm = mul2(BETA2, m);     // beta*mem   (separate rounding)
            const u64 bc = add2(bm, cp);       // + cur      (separate rounding)
            m = fma2(rp, NEG2, bc);            // - reset
            float mlo, mhi; unpack2(m, mlo, mhi);
            const float slo = fset_gt1(mlo);
            const float shi = fset_gt1(mhi);
            rp = pack2(slo, shi);
            // packed acc: lane0 out0, lane1 out1; serial h order: 2p then 2p+1
            accP[t] = fma2(pack2(slo, slo), wA, accP[t]);
            accP[t] = fma2(pack2(shi, shi), wB, accP[t]);
        }
    }

    // Output layer recurrence + coalesced float2 stores.
    const float b20 = __ldg(&b2[0]);
    const float b21 = __ldg(&b2[1]);
    float m0 = 0.0f, m1 = 0.0f;
    float s0 = 0.0f, s1 = 0.0f;   // spike == next step's reset

    float2* pspk = (float2*)out + (size_t)b;                          // spk2_rec [25,B,2]
    float2* pmem = (float2*)out + (size_t)TSTEPS * BATCH + (size_t)b; // mem2_rec [25,B,2]

    #pragma unroll
    for (int t = 0; t < TSTEPS; t++) {
        float a0, a1; unpack2(accP[t], a0, a1);
        const float c0 = __fadd_rn(a0, b20);
        const float c1 = __fadd_rn(a1, b21);

        m0 = __fsub_rn(__fadd_rn(__fmul_rn(BETA, m0), c0), s0);
        s0 = fset_gt1(m0);

        m1 = __fsub_rn(__fadd_rn(__fmul_rn(BETA, m1), c1), s1);
        s1 = fset_gt1(m1);

        pspk[(size_t)t * BATCH] = make_float2(s0, s1);
        pmem[(size_t)t * BATCH] = make_float2(m0, m1);
    }
}

extern "C" void kernel_launch(void* const* d_in, const int* in_sizes, int n_in,
                              void* d_out, int out_size) {
    const float* x  = (const float*)d_in[0];
    const float* W1 = (const float*)d_in[1];
    const float* b1 = (const float*)d_in[2];
    const float* W2 = (const float*)d_in[3];
    const float* b2 = (const float*)d_in[4];
    float* out = (float*)d_out;

    const int threads = 128;
    snn_kernel<<<BATCH / threads, threads>>>(x, W1, b1, W2, b2, out);
}